// round 5
// baseline (speedup 1.0000x reference)
#include <cuda_runtime.h>
#include <math.h>

#define NN    100000
#define NE    1200000
#define F_IN  64
#define F_HID 16
#define F_OUT 40

#define SCAN_BS 1024
#define NBLK    ((NN + SCAN_BS - 1) / SCAN_BS)   // 98

// ---- scratch (static device globals; referenced ONLY from device code) ----
__device__ float g_xs  [NN * F_HID];   // x @ W1_self + b1
__device__ float g_xn  [NN * F_HID];   // x @ W1_neigh
__device__ float g_h   [NN * F_HID];   // hidden activations
__device__ int   g_cnt   [NN];         // in-degree
__device__ int   g_off   [NN];         // CSR offsets (exclusive scan of cnt)
__device__ int   g_cursor[NN];         // scatter cursors
__device__ int   g_eidx  [NE];         // src ids bucketed by dst
__device__ int   g_sagg  [NBLK];       // scan: block aggregates
__device__ int   g_spre  [NBLK];       // scan: inclusive prefixes
__device__ int   g_sflag [NBLK];       // scan: 0=invalid 1=agg 2=prefix

// ---------------------------------------------------------------------------
// Kernel 0: zero degree counters + scan flags
// ---------------------------------------------------------------------------
__global__ __launch_bounds__(256)
void k_zero(int n)
{
    int i = blockIdx.x * blockDim.x + threadIdx.x;
    if (i < n) g_cnt[i] = 0;
    if (i < NBLK) g_sflag[i] = 0;
}

// ---------------------------------------------------------------------------
// Kernel 1: fused layer-1 projections + degree histogram.
// Grid covers all E edges; the first ceil(N/256) blocks also do the node GEMM.
// ---------------------------------------------------------------------------
__global__ __launch_bounds__(256)
void k_lin1_count(const float* __restrict__ x,
                  const int*   __restrict__ ei,
                  const float* __restrict__ W1s,
                  const float* __restrict__ W1n,
                  const float* __restrict__ b1,
                  int n, int e)
{
    int t = blockIdx.x * blockDim.x + threadIdx.x;

    // edge histogram part (all blocks)
    if (t < e) {
        int dst = __ldg(ei + e + t);
        atomicAdd(g_cnt + dst, 1);
    }

    // node GEMM part (only blocks overlapping [0, n))
    if (blockIdx.x * blockDim.x >= (unsigned)n) return;

    __shared__ float4 sWs[F_IN * (F_HID / 4)];   // [k][jb]
    __shared__ float4 sWn[F_IN * (F_HID / 4)];
    for (int i = threadIdx.x; i < F_IN * F_HID; i += blockDim.x) {
        ((float*)sWs)[i] = W1s[i];
        ((float*)sWn)[i] = W1n[i];
    }
    __syncthreads();

    int node = t;
    if (node >= n) return;

    float4 z = make_float4(0.f, 0.f, 0.f, 0.f);
    float4 accS[4], accN[4];
    const float4* b1v = (const float4*)b1;
#pragma unroll
    for (int jb = 0; jb < 4; jb++) { accS[jb] = __ldg(b1v + jb); accN[jb] = z; }

    const float4* xrow = (const float4*)x + node * (F_IN / 4);
#pragma unroll 1
    for (int kb = 0; kb < F_IN / 4; kb++) {
        float4 xv = __ldg(xrow + kb);
        float xk[4] = { xv.x, xv.y, xv.z, xv.w };
#pragma unroll
        for (int kk = 0; kk < 4; kk++) {
            int k = kb * 4 + kk;
            float xs = xk[kk];
#pragma unroll
            for (int jb = 0; jb < 4; jb++) {
                float4 ws = sWs[k * 4 + jb];
                float4 wn = sWn[k * 4 + jb];
                accS[jb].x += xs * ws.x; accS[jb].y += xs * ws.y;
                accS[jb].z += xs * ws.z; accS[jb].w += xs * ws.w;
                accN[jb].x += xs * wn.x; accN[jb].y += xs * wn.y;
                accN[jb].z += xs * wn.z; accN[jb].w += xs * wn.w;
            }
        }
    }

    float4* xsrow = (float4*)g_xs + node * 4;
    float4* xnrow = (float4*)g_xn + node * 4;
#pragma unroll
    for (int jb = 0; jb < 4; jb++) { xsrow[jb] = accS[jb]; xnrow[jb] = accN[jb]; }
}

// ---------------------------------------------------------------------------
// Kernel 2: single-pass exclusive scan (decoupled lookback) of g_cnt.
// Writes g_off and g_cursor. 98 blocks x 1024 threads (all co-resident).
// ---------------------------------------------------------------------------
__global__ __launch_bounds__(SCAN_BS)
void k_scan()
{
    const unsigned FULL = 0xffffffffu;
    int b = blockIdx.x;
    int tid = threadIdx.x;
    int lane = tid & 31, wid = tid >> 5;
    int i = b * SCAN_BS + tid;

    int v = (i < NN) ? g_cnt[i] : 0;

    // warp inclusive scan
    int s = v;
#pragma unroll
    for (int o = 1; o < 32; o <<= 1) {
        int t = __shfl_up_sync(FULL, s, o);
        if (lane >= o) s += t;
    }
    __shared__ int wsum[32];
    if (lane == 31) wsum[wid] = s;
    __syncthreads();
    if (wid == 0) {
        int w = wsum[lane];
#pragma unroll
        for (int o = 1; o < 32; o <<= 1) {
            int t = __shfl_up_sync(FULL, w, o);
            if (lane >= o) w += t;
        }
        wsum[lane] = w;
    }
    __syncthreads();
    int incl  = s + ((wid > 0) ? wsum[wid - 1] : 0);   // inclusive within block
    int total = wsum[31];

    __shared__ int s_exc;

    if (tid == 0) {
        if (b == 0) {
            *(volatile int*)&g_spre[0] = total;
            __threadfence();
            *(volatile int*)&g_sflag[0] = 2;
            s_exc = 0;
        } else {
            *(volatile int*)&g_sagg[b] = total;
            __threadfence();
            *(volatile int*)&g_sflag[b] = 1;
        }
    }

    if (b > 0 && tid < 32) {
        int exc = 0;
        int look = b - 1;
        while (true) {
            int idx = look - lane;
            int f;
            do {
                f = (idx >= 0) ? *(volatile int*)&g_sflag[idx] : 2;
            } while (__any_sync(FULL, f == 0));
            __threadfence();
            int val = 0;
            if (idx >= 0)
                val = (f == 2) ? *(volatile int*)&g_spre[idx]
                               : *(volatile int*)&g_sagg[idx];

            unsigned pm = __ballot_sync(FULL, idx >= 0 && f == 2);
            if (pm) {
                int fp = __ffs(pm) - 1;   // smallest lane = largest idx with prefix
                int c = (lane <= fp) ? val : 0;
#pragma unroll
                for (int o = 16; o; o >>= 1) c += __shfl_xor_sync(FULL, c, o);
                exc += c;
                break;
            } else {
                int c = (idx >= 0) ? val : 0;
#pragma unroll
                for (int o = 16; o; o >>= 1) c += __shfl_xor_sync(FULL, c, o);
                exc += c;
                look -= 32;
            }
        }
        if (lane == 0) {
            s_exc = exc;
            *(volatile int*)&g_spre[b] = exc + total;
            __threadfence();
            *(volatile int*)&g_sflag[b] = 2;
        }
    }
    __syncthreads();

    int off_i = s_exc + incl - v;     // global exclusive prefix
    if (i < NN) { g_off[i] = off_i; g_cursor[i] = off_i; }
}

// ---------------------------------------------------------------------------
// Kernel 3: scatter src ids into dst buckets
// ---------------------------------------------------------------------------
__global__ __launch_bounds__(256)
void k_scatter(const int* __restrict__ ei, int e)
{
    int t = blockIdx.x * blockDim.x + threadIdx.x;
    if (t >= e) return;
    int src = __ldg(ei + t);
    int dst = __ldg(ei + e + t);
    int slot = atomicAdd(g_cursor + dst, 1);
    g_eidx[slot] = src;
}

// ---------------------------------------------------------------------------
// Kernel 4: layer-1 aggregation (warp per node) fused with hidden activation:
//   h = relu(xs + mean_neigh(xn))
// Lane layout: nb = lane>>2 (8 neighbor slots), jb = lane&3 (float4 column)
// ---------------------------------------------------------------------------
__global__ __launch_bounds__(256)
void k_agg1(int n)
{
    int warp = (blockIdx.x * blockDim.x + threadIdx.x) >> 5;
    if (warp >= n) return;
    int lane = threadIdx.x & 31;
    int nb = lane >> 2;
    int jb = lane & 3;

    int beg = g_off[warp];
    int deg = g_cnt[warp];
    int end = beg + deg;

    float4 acc = make_float4(0.f, 0.f, 0.f, 0.f);
    for (int i = beg + nb; i < end; i += 8) {
        int s = g_eidx[i];
        float4 v = ((const float4*)g_xn)[s * 4 + jb];
        acc.x += v.x; acc.y += v.y; acc.z += v.z; acc.w += v.w;
    }
#pragma unroll
    for (int off = 4; off < 32; off <<= 1) {
        acc.x += __shfl_xor_sync(0xffffffffu, acc.x, off);
        acc.y += __shfl_xor_sync(0xffffffffu, acc.y, off);
        acc.z += __shfl_xor_sync(0xffffffffu, acc.z, off);
        acc.w += __shfl_xor_sync(0xffffffffu, acc.w, off);
    }

    if (nb == 0) {
        float invd = 1.0f / fmaxf((float)deg, 1.0f);
        float4 sv = ((const float4*)g_xs)[warp * 4 + jb];
        float4 r;
        r.x = fmaxf(sv.x + acc.x * invd, 0.f);
        r.y = fmaxf(sv.y + acc.y * invd, 0.f);
        r.z = fmaxf(sv.z + acc.z * invd, 0.f);
        r.w = fmaxf(sv.w + acc.w * invd, 0.f);
        ((float4*)g_h)[warp * 4 + jb] = r;
    }
}

// ---------------------------------------------------------------------------
// Kernel 5: fused layer-2 aggregation + output GEMM + log-softmax.
// Warp per node. Gather-reduce neighbors of h, stage h/agg in smem,
// lane j computes output column j (lanes 0-7 also column 32+j).
// ---------------------------------------------------------------------------
__global__ __launch_bounds__(256)
void k_agg2_out(const float* __restrict__ W2s,
                const float* __restrict__ W2n,
                const float* __restrict__ b2,
                float* __restrict__ out,
                int n)
{
    const unsigned FULL = 0xffffffffu;
    __shared__ float sWs[F_HID * F_OUT];
    __shared__ float sWn[F_HID * F_OUT];
    __shared__ float sb[F_OUT];
    __shared__ float sh[8][F_HID];   // per-warp h row
    __shared__ float sa[8][F_HID];   // per-warp mean-agg row

    for (int i = threadIdx.x; i < F_HID * F_OUT; i += blockDim.x) {
        sWs[i] = W2s[i];
        sWn[i] = W2n[i];
    }
    for (int i = threadIdx.x; i < F_OUT; i += blockDim.x) sb[i] = b2[i];
    __syncthreads();

    int warp_g = (blockIdx.x * blockDim.x + threadIdx.x) >> 5;
    if (warp_g >= n) return;
    int wl = threadIdx.x >> 5;
    int lane = threadIdx.x & 31;
    int nb = lane >> 2;
    int jb = lane & 3;

    int beg = g_off[warp_g];
    int deg = g_cnt[warp_g];
    int end = beg + deg;

    float4 acc = make_float4(0.f, 0.f, 0.f, 0.f);
    for (int i = beg + nb; i < end; i += 8) {
        int s = g_eidx[i];
        float4 v = ((const float4*)g_h)[s * 4 + jb];
        acc.x += v.x; acc.y += v.y; acc.z += v.z; acc.w += v.w;
    }
#pragma unroll
    for (int off = 4; off < 32; off <<= 1) {
        acc.x += __shfl_xor_sync(FULL, acc.x, off);
        acc.y += __shfl_xor_sync(FULL, acc.y, off);
        acc.z += __shfl_xor_sync(FULL, acc.z, off);
        acc.w += __shfl_xor_sync(FULL, acc.w, off);
    }

    if (nb == 0) {
        float invd = 1.0f / fmaxf((float)deg, 1.0f);
        float4 hv = ((const float4*)g_h)[warp_g * 4 + jb];
        sh[wl][jb*4+0] = hv.x;  sh[wl][jb*4+1] = hv.y;
        sh[wl][jb*4+2] = hv.z;  sh[wl][jb*4+3] = hv.w;
        sa[wl][jb*4+0] = acc.x * invd;  sa[wl][jb*4+1] = acc.y * invd;
        sa[wl][jb*4+2] = acc.z * invd;  sa[wl][jb*4+3] = acc.w * invd;
    }
    __syncwarp();

    // output columns: lane -> col lane; lanes 0-7 also col 32+lane
    float v0 = sb[lane];
    float v1 = (lane < 8) ? sb[32 + lane] : -1e30f;
#pragma unroll
    for (int k = 0; k < F_HID; k++) {
        float hk = sh[wl][k];
        float ak = sa[wl][k];
        v0 += hk * sWs[k * F_OUT + lane] + ak * sWn[k * F_OUT + lane];
        if (lane < 8)
            v1 += hk * sWs[k * F_OUT + 32 + lane] + ak * sWn[k * F_OUT + 32 + lane];
    }

    // warp log-softmax over the 40 values
    float m = fmaxf(v0, v1);
#pragma unroll
    for (int o = 16; o; o >>= 1) m = fmaxf(m, __shfl_xor_sync(FULL, m, o));
    float ssum = expf(v0 - m) + ((lane < 8) ? expf(v1 - m) : 0.f);
#pragma unroll
    for (int o = 16; o; o >>= 1) ssum += __shfl_xor_sync(FULL, ssum, o);
    float lse = m + logf(ssum);

    float* orow = out + (size_t)warp_g * F_OUT;
    orow[lane] = v0 - lse;
    if (lane < 8) orow[32 + lane] = v1 - lse;
}

// ---------------------------------------------------------------------------
extern "C" void kernel_launch(void* const* d_in, const int* in_sizes, int n_in,
                              void* d_out, int out_size)
{
    const float* x   = (const float*)d_in[0];
    const int*   ei  = (const int*)  d_in[1];
    const float* W1s = (const float*)d_in[2];
    const float* W1n = (const float*)d_in[3];
    const float* b1  = (const float*)d_in[4];
    const float* W2s = (const float*)d_in[5];
    const float* W2n = (const float*)d_in[6];
    const float* b2  = (const float*)d_in[7];
    float* out = (float*)d_out;

    int n = in_sizes[0] / F_IN;   // 100000
    int e = in_sizes[1] / 2;      // 1200000

    const int TB = 256;
    int nb_node = (n + TB - 1) / TB;
    int nb_edge = (e + TB - 1) / TB;
    int nb_warp = (n * 32 + TB - 1) / TB;   // warp-per-node kernels

    k_zero      <<<nb_node, TB>>>(n);
    k_lin1_count<<<nb_edge, TB>>>(x, ei, W1s, W1n, b1, n, e);
    k_scan      <<<NBLK, SCAN_BS>>>();
    k_scatter   <<<nb_edge, TB>>>(ei, e);
    k_agg1      <<<nb_warp, TB>>>(n);
    k_agg2_out  <<<nb_warp, TB>>>(W2s, W2n, b2, out, n);
}

// round 6
// speedup vs baseline: 1.0306x; 1.0306x over previous
#include <cuda_runtime.h>
#include <math.h>

#define NN    100000
#define NE    1200000
#define F_IN  64
#define F_HID 16
#define F_OUT 40

#define SCAN_BS 1024
#define NBLK    ((NN + SCAN_BS - 1) / SCAN_BS)   // 98
#define OUT_NPB 64                               // nodes per block in k_agg2_out

// ---- scratch (static device globals; referenced ONLY from device code) ----
__device__ float g_xs  [NN * F_HID];   // x @ W1_self + b1
__device__ float g_xn  [NN * F_HID];   // x @ W1_neigh
__device__ float g_h   [NN * F_HID];   // hidden activations
__device__ int   g_cnt   [NN];         // in-degree
__device__ int   g_off   [NN];         // CSR offsets (exclusive scan of cnt)
__device__ int   g_cursor[NN];         // scatter cursors
__device__ int   g_eidx  [NE];         // src ids bucketed by dst
__device__ int   g_sagg  [NBLK];       // scan: block aggregates
__device__ int   g_spre  [NBLK];       // scan: inclusive prefixes
__device__ int   g_sflag [NBLK];       // scan: 0=invalid 1=agg 2=prefix

// ---------------------------------------------------------------------------
// Kernel 1: layer-1 projections (+ zero the degree counters)
// ---------------------------------------------------------------------------
__global__ __launch_bounds__(256)
void k_lin1(const float* __restrict__ x,
            const float* __restrict__ W1s,
            const float* __restrict__ W1n,
            const float* __restrict__ b1,
            int n)
{
    __shared__ float4 sWs[F_IN * (F_HID / 4)];   // [k][jb]
    __shared__ float4 sWn[F_IN * (F_HID / 4)];
    for (int i = threadIdx.x; i < F_IN * F_HID; i += blockDim.x) {
        ((float*)sWs)[i] = W1s[i];
        ((float*)sWn)[i] = W1n[i];
    }
    __syncthreads();

    int node = blockIdx.x * blockDim.x + threadIdx.x;
    if (node >= n) return;

    g_cnt[node] = 0;

    float4 z = make_float4(0.f, 0.f, 0.f, 0.f);
    float4 accS[4], accN[4];
    const float4* b1v = (const float4*)b1;
#pragma unroll
    for (int jb = 0; jb < 4; jb++) { accS[jb] = __ldg(b1v + jb); accN[jb] = z; }

    const float4* xrow = (const float4*)x + node * (F_IN / 4);
#pragma unroll 1
    for (int kb = 0; kb < F_IN / 4; kb++) {
        float4 xv = __ldg(xrow + kb);
        float xk[4] = { xv.x, xv.y, xv.z, xv.w };
#pragma unroll
        for (int kk = 0; kk < 4; kk++) {
            int k = kb * 4 + kk;
            float xs = xk[kk];
#pragma unroll
            for (int jb = 0; jb < 4; jb++) {
                float4 ws = sWs[k * 4 + jb];
                float4 wn = sWn[k * 4 + jb];
                accS[jb].x += xs * ws.x; accS[jb].y += xs * ws.y;
                accS[jb].z += xs * ws.z; accS[jb].w += xs * ws.w;
                accN[jb].x += xs * wn.x; accN[jb].y += xs * wn.y;
                accN[jb].z += xs * wn.z; accN[jb].w += xs * wn.w;
            }
        }
    }

    float4* xsrow = (float4*)g_xs + node * 4;
    float4* xnrow = (float4*)g_xn + node * 4;
#pragma unroll
    for (int jb = 0; jb < 4; jb++) { xsrow[jb] = accS[jb]; xnrow[jb] = accN[jb]; }
}

// ---------------------------------------------------------------------------
// Kernel 2: degree histogram over dst (+ reset scan flags)
// ---------------------------------------------------------------------------
__global__ __launch_bounds__(256)
void k_count(const int* __restrict__ ei, int e)
{
    int t = blockIdx.x * blockDim.x + threadIdx.x;
    if (t < NBLK) g_sflag[t] = 0;
    if (t >= e) return;
    int dst = __ldg(ei + e + t);
    atomicAdd(g_cnt + dst, 1);
}

// ---------------------------------------------------------------------------
// Kernel 3: single-pass exclusive scan (decoupled lookback) of g_cnt.
// Writes g_off and g_cursor. 98 blocks x 1024 threads (all co-resident).
// ---------------------------------------------------------------------------
__global__ __launch_bounds__(SCAN_BS)
void k_scan()
{
    const unsigned FULL = 0xffffffffu;
    int b = blockIdx.x;
    int tid = threadIdx.x;
    int lane = tid & 31, wid = tid >> 5;
    int i = b * SCAN_BS + tid;

    int v = (i < NN) ? g_cnt[i] : 0;

    // warp inclusive scan
    int s = v;
#pragma unroll
    for (int o = 1; o < 32; o <<= 1) {
        int t = __shfl_up_sync(FULL, s, o);
        if (lane >= o) s += t;
    }
    __shared__ int wsum[32];
    if (lane == 31) wsum[wid] = s;
    __syncthreads();
    if (wid == 0) {
        int w = wsum[lane];
#pragma unroll
        for (int o = 1; o < 32; o <<= 1) {
            int t = __shfl_up_sync(FULL, w, o);
            if (lane >= o) w += t;
        }
        wsum[lane] = w;
    }
    __syncthreads();
    int incl  = s + ((wid > 0) ? wsum[wid - 1] : 0);   // inclusive within block
    int total = wsum[31];

    __shared__ int s_exc;

    if (tid == 0) {
        if (b == 0) {
            *(volatile int*)&g_spre[0] = total;
            __threadfence();
            *(volatile int*)&g_sflag[0] = 2;
            s_exc = 0;
        } else {
            *(volatile int*)&g_sagg[b] = total;
            __threadfence();
            *(volatile int*)&g_sflag[b] = 1;
        }
    }

    if (b > 0 && tid < 32) {
        int exc = 0;
        int look = b - 1;
        while (true) {
            int idx = look - lane;
            int f;
            do {
                f = (idx >= 0) ? *(volatile int*)&g_sflag[idx] : 2;
            } while (__any_sync(FULL, f == 0));
            __threadfence();
            int val = 0;
            if (idx >= 0)
                val = (f == 2) ? *(volatile int*)&g_spre[idx]
                               : *(volatile int*)&g_sagg[idx];

            unsigned pm = __ballot_sync(FULL, idx >= 0 && f == 2);
            if (pm) {
                int fp = __ffs(pm) - 1;   // smallest lane = largest idx with prefix
                int c = (lane <= fp) ? val : 0;
#pragma unroll
                for (int o = 16; o; o >>= 1) c += __shfl_xor_sync(FULL, c, o);
                exc += c;
                break;
            } else {
                int c = (idx >= 0) ? val : 0;
#pragma unroll
                for (int o = 16; o; o >>= 1) c += __shfl_xor_sync(FULL, c, o);
                exc += c;
                look -= 32;
            }
        }
        if (lane == 0) {
            s_exc = exc;
            *(volatile int*)&g_spre[b] = exc + total;
            __threadfence();
            *(volatile int*)&g_sflag[b] = 2;
        }
    }
    __syncthreads();

    int off_i = s_exc + incl - v;     // global exclusive prefix
    if (i < NN) { g_off[i] = off_i; g_cursor[i] = off_i; }
}

// ---------------------------------------------------------------------------
// Kernel 4: scatter src ids into dst buckets
// ---------------------------------------------------------------------------
__global__ __launch_bounds__(256)
void k_scatter(const int* __restrict__ ei, int e)
{
    int t = blockIdx.x * blockDim.x + threadIdx.x;
    if (t >= e) return;
    int src = __ldg(ei + t);
    int dst = __ldg(ei + e + t);
    int slot = atomicAdd(g_cursor + dst, 1);
    g_eidx[slot] = src;
}

// ---------------------------------------------------------------------------
// Kernel 5: layer-1 aggregation (warp per node) fused with hidden activation:
//   h = relu(xs + mean_neigh(xn))
// Lane layout: nb = lane>>2 (8 neighbor slots), jb = lane&3 (float4 column)
// ---------------------------------------------------------------------------
__global__ __launch_bounds__(256)
void k_agg1(int n)
{
    int warp = (blockIdx.x * blockDim.x + threadIdx.x) >> 5;
    if (warp >= n) return;
    int lane = threadIdx.x & 31;
    int nb = lane >> 2;
    int jb = lane & 3;

    int beg = g_off[warp];
    int deg = g_cnt[warp];
    int end = beg + deg;

    float4 acc = make_float4(0.f, 0.f, 0.f, 0.f);
    for (int i = beg + nb; i < end; i += 8) {
        int s = g_eidx[i];
        float4 v = ((const float4*)g_xn)[s * 4 + jb];
        acc.x += v.x; acc.y += v.y; acc.z += v.z; acc.w += v.w;
    }
#pragma unroll
    for (int off = 4; off < 32; off <<= 1) {
        acc.x += __shfl_xor_sync(0xffffffffu, acc.x, off);
        acc.y += __shfl_xor_sync(0xffffffffu, acc.y, off);
        acc.z += __shfl_xor_sync(0xffffffffu, acc.z, off);
        acc.w += __shfl_xor_sync(0xffffffffu, acc.w, off);
    }

    if (nb == 0) {
        float invd = 1.0f / fmaxf((float)deg, 1.0f);
        float4 sv = ((const float4*)g_xs)[warp * 4 + jb];
        float4 r;
        r.x = fmaxf(sv.x + acc.x * invd, 0.f);
        r.y = fmaxf(sv.y + acc.y * invd, 0.f);
        r.z = fmaxf(sv.z + acc.z * invd, 0.f);
        r.w = fmaxf(sv.w + acc.w * invd, 0.f);
        ((float4*)g_h)[warp * 4 + jb] = r;
    }
}

// ---------------------------------------------------------------------------
// Kernel 6: fused layer-2 aggregation + output GEMM + log-softmax.
// 256-thread block processes OUT_NPB=64 nodes (8 warps x 8 iterations) so the
// 5.2KB weight smem load is amortized over 64 nodes (1563 blocks total).
// Warp per node per iteration; same 12,500-warp gather parallelism as k_agg1.
// ---------------------------------------------------------------------------
__global__ __launch_bounds__(256)
void k_agg2_out(const float* __restrict__ W2s,
                const float* __restrict__ W2n,
                const float* __restrict__ b2,
                float* __restrict__ out,
                int n)
{
    const unsigned FULL = 0xffffffffu;
    __shared__ float sWs[F_HID * F_OUT];
    __shared__ float sWn[F_HID * F_OUT];
    __shared__ float sb[F_OUT];
    __shared__ float sh[8][F_HID];   // per-warp h row
    __shared__ float sa[8][F_HID];   // per-warp mean-agg row

    for (int i = threadIdx.x; i < F_HID * F_OUT; i += blockDim.x) {
        sWs[i] = W2s[i];
        sWn[i] = W2n[i];
    }
    if (threadIdx.x < F_OUT) sb[threadIdx.x] = b2[threadIdx.x];
    __syncthreads();

    int wl   = threadIdx.x >> 5;
    int lane = threadIdx.x & 31;
    int nb = lane >> 2;
    int jb = lane & 3;
    int base = blockIdx.x * OUT_NPB;

#pragma unroll 1
    for (int it = 0; it < OUT_NPB / 8; it++) {
        int node = base + it * 8 + wl;
        if (node >= n) break;   // node grows monotonically per warp

        int beg = g_off[node];
        int deg = g_cnt[node];
        int end = beg + deg;

        float4 acc = make_float4(0.f, 0.f, 0.f, 0.f);
        for (int i = beg + nb; i < end; i += 8) {
            int s = g_eidx[i];
            float4 v = ((const float4*)g_h)[s * 4 + jb];
            acc.x += v.x; acc.y += v.y; acc.z += v.z; acc.w += v.w;
        }
#pragma unroll
        for (int off = 4; off < 32; off <<= 1) {
            acc.x += __shfl_xor_sync(FULL, acc.x, off);
            acc.y += __shfl_xor_sync(FULL, acc.y, off);
            acc.z += __shfl_xor_sync(FULL, acc.z, off);
            acc.w += __shfl_xor_sync(FULL, acc.w, off);
        }

        if (nb == 0) {
            float invd = 1.0f / fmaxf((float)deg, 1.0f);
            float4 hv = ((const float4*)g_h)[node * 4 + jb];
            sh[wl][jb*4+0] = hv.x;  sh[wl][jb*4+1] = hv.y;
            sh[wl][jb*4+2] = hv.z;  sh[wl][jb*4+3] = hv.w;
            sa[wl][jb*4+0] = acc.x * invd;  sa[wl][jb*4+1] = acc.y * invd;
            sa[wl][jb*4+2] = acc.z * invd;  sa[wl][jb*4+3] = acc.w * invd;
        }
        __syncwarp();

        // output columns: lane -> col lane; lanes 0-7 also col 32+lane
        float v0 = sb[lane];
        float v1 = (lane < 8) ? sb[32 + lane] : -1e30f;
#pragma unroll
        for (int k = 0; k < F_HID; k++) {
            float hk = sh[wl][k];
            float ak = sa[wl][k];
            v0 += hk * sWs[k * F_OUT + lane] + ak * sWn[k * F_OUT + lane];
            if (lane < 8)
                v1 += hk * sWs[k * F_OUT + 32 + lane] + ak * sWn[k * F_OUT + 32 + lane];
        }

        // warp log-softmax over the 40 values
        float m = fmaxf(v0, v1);
#pragma unroll
        for (int o = 16; o; o >>= 1) m = fmaxf(m, __shfl_xor_sync(FULL, m, o));
        float ssum = expf(v0 - m) + ((lane < 8) ? expf(v1 - m) : 0.f);
#pragma unroll
        for (int o = 16; o; o >>= 1) ssum += __shfl_xor_sync(FULL, ssum, o);
        float lse = m + logf(ssum);

        float* orow = out + (size_t)node * F_OUT;
        orow[lane] = v0 - lse;
        if (lane < 8) orow[32 + lane] = v1 - lse;
        __syncwarp();   // protect sh/sa before next iteration overwrites
    }
}

// ---------------------------------------------------------------------------
extern "C" void kernel_launch(void* const* d_in, const int* in_sizes, int n_in,
                              void* d_out, int out_size)
{
    const float* x   = (const float*)d_in[0];
    const int*   ei  = (const int*)  d_in[1];
    const float* W1s = (const float*)d_in[2];
    const float* W1n = (const float*)d_in[3];
    const float* b1  = (const float*)d_in[4];
    const float* W2s = (const float*)d_in[5];
    const float* W2n = (const float*)d_in[6];
    const float* b2  = (const float*)d_in[7];
    float* out = (float*)d_out;

    int n = in_sizes[0] / F_IN;   // 100000
    int e = in_sizes[1] / 2;      // 1200000

    const int TB = 256;
    int nb_node = (n + TB - 1) / TB;
    int nb_edge = (e + TB - 1) / TB;
    int nb_warp = (n * 32 + TB - 1) / TB;          // warp-per-node kernel
    int nb_out  = (n + OUT_NPB - 1) / OUT_NPB;     // fused output kernel

    k_lin1    <<<nb_node, TB>>>(x, W1s, W1n, b1, n);
    k_count   <<<nb_edge, TB>>>(ei, e);
    k_scan    <<<NBLK, SCAN_BS>>>();
    k_scatter <<<nb_edge, TB>>>(ei, e);
    k_agg1    <<<nb_warp, TB>>>(n);
    k_agg2_out<<<nb_out, TB>>>(W2s, W2n, b2, out, n);
}

// round 7
// speedup vs baseline: 1.0326x; 1.0019x over previous
#include <cuda_runtime.h>
#include <math.h>

#define NN    100000
#define NE    1200000
#define F_IN  64
#define F_HID 16
#define F_OUT 40

#define SCAN_BS 1024
#define NBLK    ((NN + SCAN_BS - 1) / SCAN_BS)   // 98
#define OUT_NPB 64                               // nodes per block in k_agg2_out

// ---- scratch (static device globals; referenced ONLY from device code) ----
__device__ float g_xs  [NN * F_HID];   // x @ W1_self + b1
__device__ float g_xn  [NN * F_HID];   // x @ W1_neigh
__device__ float g_h   [NN * F_HID];   // hidden activations
__device__ int   g_cnt   [NN];         // in-degree
__device__ int   g_off   [NN];         // CSR offsets (exclusive scan of cnt)
__device__ int   g_cursor[NN];         // scatter cursors
__device__ int   g_eidx  [NE];         // src ids bucketed by dst
__device__ int   g_bsum  [128];        // scan block sums

// ---------------------------------------------------------------------------
// Kernel 1: layer-1 projections (+ zero the degree counters)
// ---------------------------------------------------------------------------
__global__ __launch_bounds__(256)
void k_lin1(const float* __restrict__ x,
            const float* __restrict__ W1s,
            const float* __restrict__ W1n,
            const float* __restrict__ b1,
            int n)
{
    __shared__ float4 sWs[F_IN * (F_HID / 4)];   // [k][jb]
    __shared__ float4 sWn[F_IN * (F_HID / 4)];
    for (int i = threadIdx.x; i < F_IN * F_HID; i += blockDim.x) {
        ((float*)sWs)[i] = W1s[i];
        ((float*)sWn)[i] = W1n[i];
    }
    __syncthreads();

    int node = blockIdx.x * blockDim.x + threadIdx.x;
    if (node >= n) return;

    g_cnt[node] = 0;

    float4 z = make_float4(0.f, 0.f, 0.f, 0.f);
    float4 accS[4], accN[4];
    const float4* b1v = (const float4*)b1;
#pragma unroll
    for (int jb = 0; jb < 4; jb++) { accS[jb] = __ldg(b1v + jb); accN[jb] = z; }

    const float4* xrow = (const float4*)x + node * (F_IN / 4);
#pragma unroll 1
    for (int kb = 0; kb < F_IN / 4; kb++) {
        float4 xv = __ldg(xrow + kb);
        float xk[4] = { xv.x, xv.y, xv.z, xv.w };
#pragma unroll
        for (int kk = 0; kk < 4; kk++) {
            int k = kb * 4 + kk;
            float xs = xk[kk];
#pragma unroll
            for (int jb = 0; jb < 4; jb++) {
                float4 ws = sWs[k * 4 + jb];
                float4 wn = sWn[k * 4 + jb];
                accS[jb].x += xs * ws.x; accS[jb].y += xs * ws.y;
                accS[jb].z += xs * ws.z; accS[jb].w += xs * ws.w;
                accN[jb].x += xs * wn.x; accN[jb].y += xs * wn.y;
                accN[jb].z += xs * wn.z; accN[jb].w += xs * wn.w;
            }
        }
    }

    float4* xsrow = (float4*)g_xs + node * 4;
    float4* xnrow = (float4*)g_xn + node * 4;
#pragma unroll
    for (int jb = 0; jb < 4; jb++) { xsrow[jb] = accS[jb]; xnrow[jb] = accN[jb]; }
}

// ---------------------------------------------------------------------------
// Kernel 2: degree histogram over dst
// ---------------------------------------------------------------------------
__global__ __launch_bounds__(256)
void k_count(const int* __restrict__ ei, int e)
{
    int t = blockIdx.x * blockDim.x + threadIdx.x;
    if (t >= e) return;
    int dst = __ldg(ei + e + t);
    atomicAdd(g_cnt + dst, 1);
}

// ---------------------------------------------------------------------------
// Kernel 3a: per-block scan -> exclusive-within-block offsets + block totals
// ---------------------------------------------------------------------------
__global__ __launch_bounds__(SCAN_BS)
void k_scan1()
{
    __shared__ int s[SCAN_BS];
    int i = blockIdx.x * SCAN_BS + threadIdx.x;
    int v = (i < NN) ? g_cnt[i] : 0;
    s[threadIdx.x] = v;
    __syncthreads();
#pragma unroll
    for (int off = 1; off < SCAN_BS; off <<= 1) {
        int t = (threadIdx.x >= off) ? s[threadIdx.x - off] : 0;
        __syncthreads();
        s[threadIdx.x] += t;
        __syncthreads();
    }
    if (i < NN) g_off[i] = s[threadIdx.x] - v;          // exclusive within block
    if (threadIdx.x == SCAN_BS - 1) g_bsum[blockIdx.x] = s[SCAN_BS - 1];
}

// ---------------------------------------------------------------------------
// Kernel 3b (merged scan2+scan3): every block redundantly warp-scans the 98
// block totals (L2-resident, trivial), then applies offsets + inits cursors.
// ---------------------------------------------------------------------------
__global__ __launch_bounds__(256)
void k_scan23(int n)
{
    __shared__ int sexc[128];
    int tid = threadIdx.x;
    if (tid < 32) {
        const unsigned FULL = 0xffffffffu;
        int base = 0;
#pragma unroll
        for (int c = 0; c < 4; c++) {
            int idx = c * 32 + tid;
            int v = (idx < NBLK) ? g_bsum[idx] : 0;
            int sc = v;
#pragma unroll
            for (int o = 1; o < 32; o <<= 1) {
                int t = __shfl_up_sync(FULL, sc, o);
                if (tid >= o) sc += t;
            }
            sexc[idx] = base + sc - v;                 // exclusive prefix
            base += __shfl_sync(FULL, sc, 31);
        }
    }
    __syncthreads();

    int i = blockIdx.x * blockDim.x + tid;
    if (i >= n) return;
    int o = g_off[i] + sexc[i / SCAN_BS];
    g_off[i] = o;
    g_cursor[i] = o;
}

// ---------------------------------------------------------------------------
// Kernel 4: scatter src ids into dst buckets
// ---------------------------------------------------------------------------
__global__ __launch_bounds__(256)
void k_scatter(const int* __restrict__ ei, int e)
{
    int t = blockIdx.x * blockDim.x + threadIdx.x;
    if (t >= e) return;
    int src = __ldg(ei + t);
    int dst = __ldg(ei + e + t);
    int slot = atomicAdd(g_cursor + dst, 1);
    g_eidx[slot] = src;
}

// ---------------------------------------------------------------------------
// Kernel 5: layer-1 aggregation (warp per node) fused with hidden activation:
//   h = relu(xs + mean_neigh(xn))
// Lane layout: nb = lane>>2 (8 neighbor slots), jb = lane&3 (float4 column)
// ---------------------------------------------------------------------------
__global__ __launch_bounds__(256)
void k_agg1(int n)
{
    int warp = (blockIdx.x * blockDim.x + threadIdx.x) >> 5;
    if (warp >= n) return;
    int lane = threadIdx.x & 31;
    int nb = lane >> 2;
    int jb = lane & 3;

    int beg = g_off[warp];
    int deg = g_cnt[warp];
    int end = beg + deg;

    float4 acc = make_float4(0.f, 0.f, 0.f, 0.f);
    for (int i = beg + nb; i < end; i += 8) {
        int s = g_eidx[i];
        float4 v = ((const float4*)g_xn)[s * 4 + jb];
        acc.x += v.x; acc.y += v.y; acc.z += v.z; acc.w += v.w;
    }
#pragma unroll
    for (int off = 4; off < 32; off <<= 1) {
        acc.x += __shfl_xor_sync(0xffffffffu, acc.x, off);
        acc.y += __shfl_xor_sync(0xffffffffu, acc.y, off);
        acc.z += __shfl_xor_sync(0xffffffffu, acc.z, off);
        acc.w += __shfl_xor_sync(0xffffffffu, acc.w, off);
    }

    if (nb == 0) {
        float invd = 1.0f / fmaxf((float)deg, 1.0f);
        float4 sv = ((const float4*)g_xs)[warp * 4 + jb];
        float4 r;
        r.x = fmaxf(sv.x + acc.x * invd, 0.f);
        r.y = fmaxf(sv.y + acc.y * invd, 0.f);
        r.z = fmaxf(sv.z + acc.z * invd, 0.f);
        r.w = fmaxf(sv.w + acc.w * invd, 0.f);
        ((float4*)g_h)[warp * 4 + jb] = r;
    }
}

// ---------------------------------------------------------------------------
// Kernel 6: fused layer-2 aggregation + output GEMM + log-softmax.
// 256-thread block processes OUT_NPB=64 nodes (8 warps x 8 iterations) so the
// 5.2KB weight smem load is amortized over 64 nodes (1563 blocks total).
// ---------------------------------------------------------------------------
__global__ __launch_bounds__(256)
void k_agg2_out(const float* __restrict__ W2s,
                const float* __restrict__ W2n,
                const float* __restrict__ b2,
                float* __restrict__ out,
                int n)
{
    const unsigned FULL = 0xffffffffu;
    __shared__ float sWs[F_HID * F_OUT];
    __shared__ float sWn[F_HID * F_OUT];
    __shared__ float sb[F_OUT];
    __shared__ float sh[8][F_HID];   // per-warp h row
    __shared__ float sa[8][F_HID];   // per-warp mean-agg row

    for (int i = threadIdx.x; i < F_HID * F_OUT; i += blockDim.x) {
        sWs[i] = W2s[i];
        sWn[i] = W2n[i];
    }
    if (threadIdx.x < F_OUT) sb[threadIdx.x] = b2[threadIdx.x];
    __syncthreads();

    int wl   = threadIdx.x >> 5;
    int lane = threadIdx.x & 31;
    int nb = lane >> 2;
    int jb = lane & 3;
    int base = blockIdx.x * OUT_NPB;

#pragma unroll 1
    for (int it = 0; it < OUT_NPB / 8; it++) {
        int node = base + it * 8 + wl;
        if (node >= n) break;   // node grows monotonically per warp

        int beg = g_off[node];
        int deg = g_cnt[node];
        int end = beg + deg;

        float4 acc = make_float4(0.f, 0.f, 0.f, 0.f);
        for (int i = beg + nb; i < end; i += 8) {
            int s = g_eidx[i];
            float4 v = ((const float4*)g_h)[s * 4 + jb];
            acc.x += v.x; acc.y += v.y; acc.z += v.z; acc.w += v.w;
        }
#pragma unroll
        for (int off = 4; off < 32; off <<= 1) {
            acc.x += __shfl_xor_sync(FULL, acc.x, off);
            acc.y += __shfl_xor_sync(FULL, acc.y, off);
            acc.z += __shfl_xor_sync(FULL, acc.z, off);
            acc.w += __shfl_xor_sync(FULL, acc.w, off);
        }

        if (nb == 0) {
            float invd = 1.0f / fmaxf((float)deg, 1.0f);
            float4 hv = ((const float4*)g_h)[node * 4 + jb];
            sh[wl][jb*4+0] = hv.x;  sh[wl][jb*4+1] = hv.y;
            sh[wl][jb*4+2] = hv.z;  sh[wl][jb*4+3] = hv.w;
            sa[wl][jb*4+0] = acc.x * invd;  sa[wl][jb*4+1] = acc.y * invd;
            sa[wl][jb*4+2] = acc.z * invd;  sa[wl][jb*4+3] = acc.w * invd;
        }
        __syncwarp();

        // output columns: lane -> col lane; lanes 0-7 also col 32+lane
        float v0 = sb[lane];
        float v1 = (lane < 8) ? sb[32 + lane] : -1e30f;
#pragma unroll
        for (int k = 0; k < F_HID; k++) {
            float hk = sh[wl][k];
            float ak = sa[wl][k];
            v0 += hk * sWs[k * F_OUT + lane] + ak * sWn[k * F_OUT + lane];
            if (lane < 8)
                v1 += hk * sWs[k * F_OUT + 32 + lane] + ak * sWn[k * F_OUT + 32 + lane];
        }

        // warp log-softmax over the 40 values
        float m = fmaxf(v0, v1);
#pragma unroll
        for (int o = 16; o; o >>= 1) m = fmaxf(m, __shfl_xor_sync(FULL, m, o));
        float ssum = expf(v0 - m) + ((lane < 8) ? expf(v1 - m) : 0.f);
#pragma unroll
        for (int o = 16; o; o >>= 1) ssum += __shfl_xor_sync(FULL, ssum, o);
        float lse = m + logf(ssum);

        float* orow = out + (size_t)node * F_OUT;
        orow[lane] = v0 - lse;
        if (lane < 8) orow[32 + lane] = v1 - lse;
        __syncwarp();   // protect sh/sa before next iteration overwrites
    }
}

// ---------------------------------------------------------------------------
extern "C" void kernel_launch(void* const* d_in, const int* in_sizes, int n_in,
                              void* d_out, int out_size)
{
    const float* x   = (const float*)d_in[0];
    const int*   ei  = (const int*)  d_in[1];
    const float* W1s = (const float*)d_in[2];
    const float* W1n = (const float*)d_in[3];
    const float* b1  = (const float*)d_in[4];
    const float* W2s = (const float*)d_in[5];
    const float* W2n = (const float*)d_in[6];
    const float* b2  = (const float*)d_in[7];
    float* out = (float*)d_out;

    int n = in_sizes[0] / F_IN;   // 100000
    int e = in_sizes[1] / 2;      // 1200000

    const int TB = 256;
    int nb_node = (n + TB - 1) / TB;
    int nb_edge = (e + TB - 1) / TB;
    int nb_warp = (n * 32 + TB - 1) / TB;          // warp-per-node kernel
    int nb_out  = (n + OUT_NPB - 1) / OUT_NPB;     // fused output kernel

    k_lin1    <<<nb_node, TB>>>(x, W1s, W1n, b1, n);
    k_count   <<<nb_edge, TB>>>(ei, e);
    k_scan1   <<<NBLK, SCAN_BS>>>();
    k_scan23  <<<nb_node, TB>>>(n);
    k_scatter <<<nb_edge, TB>>>(ei, e);
    k_agg1    <<<nb_warp, TB>>>(n);
    k_agg2_out<<<nb_out, TB>>>(W2s, W2n, b2, out, n);
}

// round 8
// speedup vs baseline: 1.1991x; 1.1612x over previous
#include <cuda_runtime.h>
#include <math.h>

#define NN    100000
#define NE    1200000
#define F_IN  64
#define F_HID 16
#define F_OUT 40

#define SCAN_BS 1024
#define NBLK    ((NN + SCAN_BS - 1) / SCAN_BS)   // 98

// ---- scratch (static device globals; referenced ONLY from device code) ----
__device__ float g_xs  [NN * F_HID];   // x @ W1_self + b1
__device__ float g_xn  [NN * F_HID];   // x @ W1_neigh
__device__ float g_h   [NN * F_HID];   // hidden activations
__device__ float g_agg2[NN * F_HID];   // layer-2 neighbor sums
__device__ int   g_cnt   [NN];         // in-degree
__device__ int   g_off   [NN];         // CSR offsets (exclusive scan of cnt)
__device__ int   g_cursor[NN];         // scatter cursors
__device__ int   g_eidx  [NE];         // src ids bucketed by dst
__device__ int   g_bsum  [128];        // scan block sums

// ---------------------------------------------------------------------------
// Kernel 1: layer-1 projections (+ zero the degree counters)
// ---------------------------------------------------------------------------
__global__ __launch_bounds__(256)
void k_lin1(const float* __restrict__ x,
            const float* __restrict__ W1s,
            const float* __restrict__ W1n,
            const float* __restrict__ b1,
            int n)
{
    __shared__ float4 sWs[F_IN * (F_HID / 4)];   // [k][jb]
    __shared__ float4 sWn[F_IN * (F_HID / 4)];
    for (int i = threadIdx.x; i < F_IN * F_HID; i += blockDim.x) {
        ((float*)sWs)[i] = W1s[i];
        ((float*)sWn)[i] = W1n[i];
    }
    __syncthreads();

    int node = blockIdx.x * blockDim.x + threadIdx.x;
    if (node >= n) return;

    g_cnt[node] = 0;

    float4 z = make_float4(0.f, 0.f, 0.f, 0.f);
    float4 accS[4], accN[4];
    const float4* b1v = (const float4*)b1;
#pragma unroll
    for (int jb = 0; jb < 4; jb++) { accS[jb] = __ldg(b1v + jb); accN[jb] = z; }

    const float4* xrow = (const float4*)x + node * (F_IN / 4);
#pragma unroll 1
    for (int kb = 0; kb < F_IN / 4; kb++) {
        float4 xv = __ldg(xrow + kb);
        float xk[4] = { xv.x, xv.y, xv.z, xv.w };
#pragma unroll
        for (int kk = 0; kk < 4; kk++) {
            int k = kb * 4 + kk;
            float xs = xk[kk];
#pragma unroll
            for (int jb = 0; jb < 4; jb++) {
                float4 ws = sWs[k * 4 + jb];
                float4 wn = sWn[k * 4 + jb];
                accS[jb].x += xs * ws.x; accS[jb].y += xs * ws.y;
                accS[jb].z += xs * ws.z; accS[jb].w += xs * ws.w;
                accN[jb].x += xs * wn.x; accN[jb].y += xs * wn.y;
                accN[jb].z += xs * wn.z; accN[jb].w += xs * wn.w;
            }
        }
    }

    float4* xsrow = (float4*)g_xs + node * 4;
    float4* xnrow = (float4*)g_xn + node * 4;
#pragma unroll
    for (int jb = 0; jb < 4; jb++) { xsrow[jb] = accS[jb]; xnrow[jb] = accN[jb]; }
}

// ---------------------------------------------------------------------------
// Kernel 2: degree histogram over dst
// ---------------------------------------------------------------------------
__global__ __launch_bounds__(256)
void k_count(const int* __restrict__ ei, int e)
{
    int t = blockIdx.x * blockDim.x + threadIdx.x;
    if (t >= e) return;
    int dst = __ldg(ei + e + t);
    atomicAdd(g_cnt + dst, 1);
}

// ---------------------------------------------------------------------------
// Kernel 3a: per-block scan -> exclusive-within-block offsets + block totals
// ---------------------------------------------------------------------------
__global__ __launch_bounds__(SCAN_BS)
void k_scan1()
{
    __shared__ int s[SCAN_BS];
    int i = blockIdx.x * SCAN_BS + threadIdx.x;
    int v = (i < NN) ? g_cnt[i] : 0;
    s[threadIdx.x] = v;
    __syncthreads();
#pragma unroll
    for (int off = 1; off < SCAN_BS; off <<= 1) {
        int t = (threadIdx.x >= off) ? s[threadIdx.x - off] : 0;
        __syncthreads();
        s[threadIdx.x] += t;
        __syncthreads();
    }
    if (i < NN) g_off[i] = s[threadIdx.x] - v;          // exclusive within block
    if (threadIdx.x == SCAN_BS - 1) g_bsum[blockIdx.x] = s[SCAN_BS - 1];
}

// ---------------------------------------------------------------------------
// Kernel 3b (merged scan2+scan3): every block redundantly warp-scans the 98
// block totals (L2-resident, trivial), then applies offsets + inits cursors.
// ---------------------------------------------------------------------------
__global__ __launch_bounds__(256)
void k_scan23(int n)
{
    __shared__ int sexc[128];
    int tid = threadIdx.x;
    if (tid < 32) {
        const unsigned FULL = 0xffffffffu;
        int base = 0;
#pragma unroll
        for (int c = 0; c < 4; c++) {
            int idx = c * 32 + tid;
            int v = (idx < NBLK) ? g_bsum[idx] : 0;
            int sc = v;
#pragma unroll
            for (int o = 1; o < 32; o <<= 1) {
                int t = __shfl_up_sync(FULL, sc, o);
                if (tid >= o) sc += t;
            }
            sexc[idx] = base + sc - v;                 // exclusive prefix
            base += __shfl_sync(FULL, sc, 31);
        }
    }
    __syncthreads();

    int i = blockIdx.x * blockDim.x + tid;
    if (i >= n) return;
    int o = g_off[i] + sexc[i / SCAN_BS];
    g_off[i] = o;
    g_cursor[i] = o;
}

// ---------------------------------------------------------------------------
// Kernel 4: scatter src ids into dst buckets
// ---------------------------------------------------------------------------
__global__ __launch_bounds__(256)
void k_scatter(const int* __restrict__ ei, int e)
{
    int t = blockIdx.x * blockDim.x + threadIdx.x;
    if (t >= e) return;
    int src = __ldg(ei + t);
    int dst = __ldg(ei + e + t);
    int slot = atomicAdd(g_cursor + dst, 1);
    g_eidx[slot] = src;
}

// ---------------------------------------------------------------------------
// Kernel 5: layer-1 aggregation (warp per node) fused with hidden activation:
//   h = relu(xs + mean_neigh(xn))
// Lane layout: nb = lane>>2 (8 neighbor slots), jb = lane&3 (float4 column)
// ---------------------------------------------------------------------------
__global__ __launch_bounds__(256)
void k_agg1(int n)
{
    int warp = (blockIdx.x * blockDim.x + threadIdx.x) >> 5;
    if (warp >= n) return;
    int lane = threadIdx.x & 31;
    int nb = lane >> 2;
    int jb = lane & 3;

    int beg = g_off[warp];
    int deg = g_cnt[warp];
    int end = beg + deg;

    float4 acc = make_float4(0.f, 0.f, 0.f, 0.f);
    for (int i = beg + nb; i < end; i += 8) {
        int s = g_eidx[i];
        float4 v = ((const float4*)g_xn)[s * 4 + jb];
        acc.x += v.x; acc.y += v.y; acc.z += v.z; acc.w += v.w;
    }
#pragma unroll
    for (int off = 4; off < 32; off <<= 1) {
        acc.x += __shfl_xor_sync(0xffffffffu, acc.x, off);
        acc.y += __shfl_xor_sync(0xffffffffu, acc.y, off);
        acc.z += __shfl_xor_sync(0xffffffffu, acc.z, off);
        acc.w += __shfl_xor_sync(0xffffffffu, acc.w, off);
    }

    if (nb == 0) {
        float invd = 1.0f / fmaxf((float)deg, 1.0f);
        float4 sv = ((const float4*)g_xs)[warp * 4 + jb];
        float4 r;
        r.x = fmaxf(sv.x + acc.x * invd, 0.f);
        r.y = fmaxf(sv.y + acc.y * invd, 0.f);
        r.z = fmaxf(sv.z + acc.z * invd, 0.f);
        r.w = fmaxf(sv.w + acc.w * invd, 0.f);
        ((float4*)g_h)[warp * 4 + jb] = r;
    }
}

// ---------------------------------------------------------------------------
// Kernel 6: layer-2 aggregation (warp per node): agg2 = sum_neigh(h)
// ---------------------------------------------------------------------------
__global__ __launch_bounds__(256)
void k_agg2(int n)
{
    int warp = (blockIdx.x * blockDim.x + threadIdx.x) >> 5;
    if (warp >= n) return;
    int lane = threadIdx.x & 31;
    int nb = lane >> 2;
    int jb = lane & 3;

    int beg = g_off[warp];
    int end = beg + g_cnt[warp];

    float4 acc = make_float4(0.f, 0.f, 0.f, 0.f);
    for (int i = beg + nb; i < end; i += 8) {
        int s = g_eidx[i];
        float4 v = ((const float4*)g_h)[s * 4 + jb];
        acc.x += v.x; acc.y += v.y; acc.z += v.z; acc.w += v.w;
    }
#pragma unroll
    for (int off = 4; off < 32; off <<= 1) {
        acc.x += __shfl_xor_sync(0xffffffffu, acc.x, off);
        acc.y += __shfl_xor_sync(0xffffffffu, acc.y, off);
        acc.z += __shfl_xor_sync(0xffffffffu, acc.z, off);
        acc.w += __shfl_xor_sync(0xffffffffu, acc.w, off);
    }
    if (nb == 0) ((float4*)g_agg2)[warp * 4 + jb] = acc;
}

// ---------------------------------------------------------------------------
// Kernel 7: out = log_softmax(h @ W2s + (agg2/deg) @ W2n + b2)
// ---------------------------------------------------------------------------
__global__ __launch_bounds__(256)
void k_out(const float* __restrict__ W2s,
           const float* __restrict__ W2n,
           const float* __restrict__ b2,
           float* __restrict__ out,
           int n)
{
    __shared__ float4 sWs[F_HID * (F_OUT / 4)];
    __shared__ float4 sWn[F_HID * (F_OUT / 4)];
    __shared__ float4 sb[F_OUT / 4];
    for (int i = threadIdx.x; i < F_HID * F_OUT; i += blockDim.x) {
        ((float*)sWs)[i] = W2s[i];
        ((float*)sWn)[i] = W2n[i];
    }
    for (int i = threadIdx.x; i < F_OUT; i += blockDim.x) ((float*)sb)[i] = b2[i];
    __syncthreads();

    int node = blockIdx.x * blockDim.x + threadIdx.x;
    if (node >= n) return;

    float invd = 1.0f / fmaxf((float)g_cnt[node], 1.0f);

    float hk[F_HID], ak[F_HID];
    const float4* hrow = (const float4*)g_h    + node * 4;
    const float4* arow = (const float4*)g_agg2 + node * 4;
#pragma unroll
    for (int jb = 0; jb < 4; jb++) {
        float4 hv = hrow[jb];
        float4 av = arow[jb];
        hk[jb*4+0] = hv.x; hk[jb*4+1] = hv.y; hk[jb*4+2] = hv.z; hk[jb*4+3] = hv.w;
        ak[jb*4+0] = av.x * invd; ak[jb*4+1] = av.y * invd;
        ak[jb*4+2] = av.z * invd; ak[jb*4+3] = av.w * invd;
    }

    float4 acc[F_OUT / 4];
#pragma unroll
    for (int jb = 0; jb < F_OUT / 4; jb++) acc[jb] = sb[jb];

#pragma unroll
    for (int k = 0; k < F_HID; k++) {
        float hv = hk[k], av = ak[k];
#pragma unroll
        for (int jb = 0; jb < F_OUT / 4; jb++) {
            float4 ws = sWs[k * (F_OUT / 4) + jb];
            float4 wn = sWn[k * (F_OUT / 4) + jb];
            acc[jb].x += hv * ws.x + av * wn.x;
            acc[jb].y += hv * ws.y + av * wn.y;
            acc[jb].z += hv * ws.z + av * wn.z;
            acc[jb].w += hv * ws.w + av * wn.w;
        }
    }

    float m = -1e30f;
#pragma unroll
    for (int jb = 0; jb < F_OUT / 4; jb++) {
        m = fmaxf(m, fmaxf(fmaxf(acc[jb].x, acc[jb].y), fmaxf(acc[jb].z, acc[jb].w)));
    }
    float ssum = 0.f;
#pragma unroll
    for (int jb = 0; jb < F_OUT / 4; jb++) {
        ssum += expf(acc[jb].x - m) + expf(acc[jb].y - m)
              + expf(acc[jb].z - m) + expf(acc[jb].w - m);
    }
    float lse = m + logf(ssum);

    float4* orow = (float4*)(out + (size_t)node * F_OUT);
#pragma unroll
    for (int jb = 0; jb < F_OUT / 4; jb++) {
        float4 r;
        r.x = acc[jb].x - lse; r.y = acc[jb].y - lse;
        r.z = acc[jb].z - lse; r.w = acc[jb].w - lse;
        orow[jb] = r;
    }
}

// ---------------------------------------------------------------------------
extern "C" void kernel_launch(void* const* d_in, const int* in_sizes, int n_in,
                              void* d_out, int out_size)
{
    const float* x   = (const float*)d_in[0];
    const int*   ei  = (const int*)  d_in[1];
    const float* W1s = (const float*)d_in[2];
    const float* W1n = (const float*)d_in[3];
    const float* b1  = (const float*)d_in[4];
    const float* W2s = (const float*)d_in[5];
    const float* W2n = (const float*)d_in[6];
    const float* b2  = (const float*)d_in[7];
    float* out = (float*)d_out;

    int n = in_sizes[0] / F_IN;   // 100000
    int e = in_sizes[1] / 2;      // 1200000

    const int TB = 256;
    int nb_node = (n + TB - 1) / TB;
    int nb_edge = (e + TB - 1) / TB;
    int nb_warp = (n * 32 + TB - 1) / TB;   // warp-per-node kernels

    k_lin1   <<<nb_node, TB>>>(x, W1s, W1n, b1, n);
    k_count  <<<nb_edge, TB>>>(ei, e);
    k_scan1  <<<NBLK, SCAN_BS>>>();
    k_scan23 <<<nb_node, TB>>>(n);
    k_scatter<<<nb_edge, TB>>>(ei, e);
    k_agg1   <<<nb_warp, TB>>>(n);
    k_agg2   <<<nb_warp, TB>>>(n);
    k_out    <<<nb_node, TB>>>(W2s, W2n, b2, out, n);
}

// round 9
// speedup vs baseline: 1.2899x; 1.0758x over previous
#include <cuda_runtime.h>
#include <math.h>

#define NN    100000
#define NE    1200000
#define F_IN  64
#define F_HID 16
#define F_OUT 40

#define SCAN_BS 1024
#define NBLK    ((NN + SCAN_BS - 1) / SCAN_BS)   // 98

// ---- scratch (static device globals; referenced ONLY from device code) ----
// INVARIANT: g_cnt is all-zero at entry of every kernel_launch call:
//   zero-initialized at module load, and re-zeroed by k_out at the end of
//   every call (after its last use). This lets k_lin1c histogram immediately.
__device__ float g_xs  [NN * F_HID];   // x @ W1_self + b1
__device__ float g_xn  [NN * F_HID];   // x @ W1_neigh
__device__ float g_h   [NN * F_HID];   // hidden activations
__device__ float g_agg2[NN * F_HID];   // layer-2 neighbor sums
__device__ int   g_cnt [NN];           // in-degree (see invariant above)
__device__ int   g_off [NN];           // CSR offsets; scatter bumps them to END offsets
__device__ int   g_eidx[NE];           // src ids bucketed by dst
__device__ int   g_bsum[128];          // scan block sums

// ---------------------------------------------------------------------------
// Kernel 1: fused layer-1 projections + dst-degree histogram.
// Grid covers all E edges (4688 blocks); the first ceil(N/256) blocks also
// run the node GEMM. Histogram (LSU/L2-atomic) overlaps GEMM (FMA pipe).
// ---------------------------------------------------------------------------
__global__ __launch_bounds__(256)
void k_lin1c(const float* __restrict__ x,
             const int*   __restrict__ ei,
             const float* __restrict__ W1s,
             const float* __restrict__ W1n,
             const float* __restrict__ b1,
             int n, int e)
{
    int t = blockIdx.x * blockDim.x + threadIdx.x;

    // degree histogram (all blocks; g_cnt starts at zero by invariant)
    if (t < e) {
        int dst = __ldg(ei + e + t);
        atomicAdd(g_cnt + dst, 1);
    }

    // node GEMM (block-uniform early-out for pure-histogram blocks)
    if (blockIdx.x * blockDim.x >= (unsigned)n) return;

    __shared__ float4 sWs[F_IN * (F_HID / 4)];   // [k][jb]
    __shared__ float4 sWn[F_IN * (F_HID / 4)];
    for (int i = threadIdx.x; i < F_IN * F_HID; i += blockDim.x) {
        ((float*)sWs)[i] = W1s[i];
        ((float*)sWn)[i] = W1n[i];
    }
    __syncthreads();

    int node = t;
    if (node >= n) return;

    float4 z = make_float4(0.f, 0.f, 0.f, 0.f);
    float4 accS[4], accN[4];
    const float4* b1v = (const float4*)b1;
#pragma unroll
    for (int jb = 0; jb < 4; jb++) { accS[jb] = __ldg(b1v + jb); accN[jb] = z; }

    const float4* xrow = (const float4*)x + node * (F_IN / 4);
#pragma unroll 1
    for (int kb = 0; kb < F_IN / 4; kb++) {
        float4 xv = __ldg(xrow + kb);
        float xk[4] = { xv.x, xv.y, xv.z, xv.w };
#pragma unroll
        for (int kk = 0; kk < 4; kk++) {
            int k = kb * 4 + kk;
            float xs = xk[kk];
#pragma unroll
            for (int jb = 0; jb < 4; jb++) {
                float4 ws = sWs[k * 4 + jb];
                float4 wn = sWn[k * 4 + jb];
                accS[jb].x += xs * ws.x; accS[jb].y += xs * ws.y;
                accS[jb].z += xs * ws.z; accS[jb].w += xs * ws.w;
                accN[jb].x += xs * wn.x; accN[jb].y += xs * wn.y;
                accN[jb].z += xs * wn.z; accN[jb].w += xs * wn.w;
            }
        }
    }

    float4* xsrow = (float4*)g_xs + node * 4;
    float4* xnrow = (float4*)g_xn + node * 4;
#pragma unroll
    for (int jb = 0; jb < 4; jb++) { xsrow[jb] = accS[jb]; xnrow[jb] = accN[jb]; }
}

// ---------------------------------------------------------------------------
// Kernel 2a: per-block scan -> exclusive-within-block offsets + block totals
// ---------------------------------------------------------------------------
__global__ __launch_bounds__(SCAN_BS)
void k_scan1()
{
    __shared__ int s[SCAN_BS];
    int i = blockIdx.x * SCAN_BS + threadIdx.x;
    int v = (i < NN) ? g_cnt[i] : 0;
    s[threadIdx.x] = v;
    __syncthreads();
#pragma unroll
    for (int off = 1; off < SCAN_BS; off <<= 1) {
        int t = (threadIdx.x >= off) ? s[threadIdx.x - off] : 0;
        __syncthreads();
        s[threadIdx.x] += t;
        __syncthreads();
    }
    if (i < NN) g_off[i] = s[threadIdx.x] - v;          // exclusive within block
    if (threadIdx.x == SCAN_BS - 1) g_bsum[blockIdx.x] = s[SCAN_BS - 1];
}

// ---------------------------------------------------------------------------
// Kernel 2b: every block redundantly warp-scans the 98 block totals
// (L2-resident, trivial) and applies the block base to g_off.
// ---------------------------------------------------------------------------
__global__ __launch_bounds__(256)
void k_scan23(int n)
{
    __shared__ int sexc[128];
    int tid = threadIdx.x;
    if (tid < 32) {
        const unsigned FULL = 0xffffffffu;
        int base = 0;
#pragma unroll
        for (int c = 0; c < 4; c++) {
            int idx = c * 32 + tid;
            int v = (idx < NBLK) ? g_bsum[idx] : 0;
            int sc = v;
#pragma unroll
            for (int o = 1; o < 32; o <<= 1) {
                int t = __shfl_up_sync(FULL, sc, o);
                if (tid >= o) sc += t;
            }
            sexc[idx] = base + sc - v;                 // exclusive prefix
            base += __shfl_sync(FULL, sc, 31);
        }
    }
    __syncthreads();

    int i = blockIdx.x * blockDim.x + tid;
    if (i >= n) return;
    g_off[i] += sexc[i / SCAN_BS];
}

// ---------------------------------------------------------------------------
// Kernel 3: scatter src ids into dst buckets (4 edges per thread, int4 loads).
// Uses g_off itself as the cursor: after this kernel g_off[d] = END offset
// (beg + cnt); consumers recompute beg = g_off[d] - g_cnt[d].
// ---------------------------------------------------------------------------
__global__ __launch_bounds__(256)
void k_scatter(const int* __restrict__ ei, int e)
{
    int e4 = e >> 2;
    int t = blockIdx.x * blockDim.x + threadIdx.x;
    if (t < e4) {
        int4 s = __ldg((const int4*)ei + t);
        int4 d = __ldg((const int4*)(ei + e) + t);
        g_eidx[atomicAdd(g_off + d.x, 1)] = s.x;
        g_eidx[atomicAdd(g_off + d.y, 1)] = s.y;
        g_eidx[atomicAdd(g_off + d.z, 1)] = s.z;
        g_eidx[atomicAdd(g_off + d.w, 1)] = s.w;
    }
    // tail (e % 4 edges), handled by thread 0
    if (t == 0) {
        for (int i = e4 * 4; i < e; i++) {
            int s = __ldg(ei + i);
            int d = __ldg(ei + e + i);
            g_eidx[atomicAdd(g_off + d, 1)] = s;
        }
    }
}

// ---------------------------------------------------------------------------
// Kernel 4: layer-1 aggregation (warp per node) fused with hidden activation:
//   h = relu(xs + mean_neigh(xn))
// Lane layout: nb = lane>>2 (8 neighbor slots), jb = lane&3 (float4 column)
// ---------------------------------------------------------------------------
__global__ __launch_bounds__(256)
void k_agg1(int n)
{
    int warp = (blockIdx.x * blockDim.x + threadIdx.x) >> 5;
    if (warp >= n) return;
    int lane = threadIdx.x & 31;
    int nb = lane >> 2;
    int jb = lane & 3;

    int deg = g_cnt[warp];
    int end = g_off[warp];          // end offset (post-scatter)
    int beg = end - deg;

    float4 acc = make_float4(0.f, 0.f, 0.f, 0.f);
    for (int i = beg + nb; i < end; i += 8) {
        int s = g_eidx[i];
        float4 v = ((const float4*)g_xn)[s * 4 + jb];
        acc.x += v.x; acc.y += v.y; acc.z += v.z; acc.w += v.w;
    }
#pragma unroll
    for (int off = 4; off < 32; off <<= 1) {
        acc.x += __shfl_xor_sync(0xffffffffu, acc.x, off);
        acc.y += __shfl_xor_sync(0xffffffffu, acc.y, off);
        acc.z += __shfl_xor_sync(0xffffffffu, acc.z, off);
        acc.w += __shfl_xor_sync(0xffffffffu, acc.w, off);
    }

    if (nb == 0) {
        float invd = 1.0f / fmaxf((float)deg, 1.0f);
        float4 sv = ((const float4*)g_xs)[warp * 4 + jb];
        float4 r;
        r.x = fmaxf(sv.x + acc.x * invd, 0.f);
        r.y = fmaxf(sv.y + acc.y * invd, 0.f);
        r.z = fmaxf(sv.z + acc.z * invd, 0.f);
        r.w = fmaxf(sv.w + acc.w * invd, 0.f);
        ((float4*)g_h)[warp * 4 + jb] = r;
    }
}

// ---------------------------------------------------------------------------
// Kernel 5: layer-2 aggregation (warp per node): agg2 = sum_neigh(h)
// ---------------------------------------------------------------------------
__global__ __launch_bounds__(256)
void k_agg2(int n)
{
    int warp = (blockIdx.x * blockDim.x + threadIdx.x) >> 5;
    if (warp >= n) return;
    int lane = threadIdx.x & 31;
    int nb = lane >> 2;
    int jb = lane & 3;

    int end = g_off[warp];
    int beg = end - g_cnt[warp];

    float4 acc = make_float4(0.f, 0.f, 0.f, 0.f);
    for (int i = beg + nb; i < end; i += 8) {
        int s = g_eidx[i];
        float4 v = ((const float4*)g_h)[s * 4 + jb];
        acc.x += v.x; acc.y += v.y; acc.z += v.z; acc.w += v.w;
    }
#pragma unroll
    for (int off = 4; off < 32; off <<= 1) {
        acc.x += __shfl_xor_sync(0xffffffffu, acc.x, off);
        acc.y += __shfl_xor_sync(0xffffffffu, acc.y, off);
        acc.z += __shfl_xor_sync(0xffffffffu, acc.z, off);
        acc.w += __shfl_xor_sync(0xffffffffu, acc.w, off);
    }
    if (nb == 0) ((float4*)g_agg2)[warp * 4 + jb] = acc;
}

// ---------------------------------------------------------------------------
// Kernel 6: out = log_softmax(h @ W2s + (agg2/deg) @ W2n + b2)
// Also re-zeroes g_cnt (restores the entry invariant for the next call).
// ---------------------------------------------------------------------------
__global__ __launch_bounds__(256)
void k_out(const float* __restrict__ W2s,
           const float* __restrict__ W2n,
           const float* __restrict__ b2,
           float* __restrict__ out,
           int n)
{
    __shared__ float4 sWs[F_HID * (F_OUT / 4)];
    __shared__ float4 sWn[F_HID * (F_OUT / 4)];
    __shared__ float4 sb[F_OUT / 4];
    for (int i = threadIdx.x; i < F_HID * F_OUT; i += blockDim.x) {
        ((float*)sWs)[i] = W2s[i];
        ((float*)sWn)[i] = W2n[i];
    }
    for (int i = threadIdx.x; i < F_OUT; i += blockDim.x) ((float*)sb)[i] = b2[i];
    __syncthreads();

    int node = blockIdx.x * blockDim.x + threadIdx.x;
    if (node >= n) return;

    float invd = 1.0f / fmaxf((float)g_cnt[node], 1.0f);
    g_cnt[node] = 0;    // restore invariant (last use of cnt this call)

    float hk[F_HID], ak[F_HID];
    const float4* hrow = (const float4*)g_h    + node * 4;
    const float4* arow = (const float4*)g_agg2 + node * 4;
#pragma unroll
    for (int jb = 0; jb < 4; jb++) {
        float4 hv = hrow[jb];
        float4 av = arow[jb];
        hk[jb*4+0] = hv.x; hk[jb*4+1] = hv.y; hk[jb*4+2] = hv.z; hk[jb*4+3] = hv.w;
        ak[jb*4+0] = av.x * invd; ak[jb*4+1] = av.y * invd;
        ak[jb*4+2] = av.z * invd; ak[jb*4+3] = av.w * invd;
    }

    float4 acc[F_OUT / 4];
#pragma unroll
    for (int jb = 0; jb < F_OUT / 4; jb++) acc[jb] = sb[jb];

#pragma unroll
    for (int k = 0; k < F_HID; k++) {
        float hv = hk[k], av = ak[k];
#pragma unroll
        for (int jb = 0; jb < F_OUT / 4; jb++) {
            float4 ws = sWs[k * (F_OUT / 4) + jb];
            float4 wn = sWn[k * (F_OUT / 4) + jb];
            acc[jb].x += hv * ws.x + av * wn.x;
            acc[jb].y += hv * ws.y + av * wn.y;
            acc[jb].z += hv * ws.z + av * wn.z;
            acc[jb].w += hv * ws.w + av * wn.w;
        }
    }

    float m = -1e30f;
#pragma unroll
    for (int jb = 0; jb < F_OUT / 4; jb++) {
        m = fmaxf(m, fmaxf(fmaxf(acc[jb].x, acc[jb].y), fmaxf(acc[jb].z, acc[jb].w)));
    }
    float ssum = 0.f;
#pragma unroll
    for (int jb = 0; jb < F_OUT / 4; jb++) {
        ssum += expf(acc[jb].x - m) + expf(acc[jb].y - m)
              + expf(acc[jb].z - m) + expf(acc[jb].w - m);
    }
    float lse = m + logf(ssum);

    float4* orow = (float4*)(out + (size_t)node * F_OUT);
#pragma unroll
    for (int jb = 0; jb < F_OUT / 4; jb++) {
        float4 r;
        r.x = acc[jb].x - lse; r.y = acc[jb].y - lse;
        r.z = acc[jb].z - lse; r.w = acc[jb].w - lse;
        orow[jb] = r;
    }
}

// ---------------------------------------------------------------------------
extern "C" void kernel_launch(void* const* d_in, const int* in_sizes, int n_in,
                              void* d_out, int out_size)
{
    const float* x   = (const float*)d_in[0];
    const int*   ei  = (const int*)  d_in[1];
    const float* W1s = (const float*)d_in[2];
    const float* W1n = (const float*)d_in[3];
    const float* b1  = (const float*)d_in[4];
    const float* W2s = (const float*)d_in[5];
    const float* W2n = (const float*)d_in[6];
    const float* b2  = (const float*)d_in[7];
    float* out = (float*)d_out;

    int n = in_sizes[0] / F_IN;   // 100000
    int e = in_sizes[1] / 2;      // 1200000

    const int TB = 256;
    int nb_node = (n + TB - 1) / TB;
    int nb_edge = (e + TB - 1) / TB;
    int nb_sct  = ((e >> 2) + TB - 1) / TB;
    int nb_warp = (n * 32 + TB - 1) / TB;   // warp-per-node kernels

    k_lin1c  <<<nb_edge, TB>>>(x, ei, W1s, W1n, b1, n, e);
    k_scan1  <<<NBLK, SCAN_BS>>>();
    k_scan23 <<<nb_node, TB>>>(n);
    k_scatter<<<nb_sct, TB>>>(ei, e);
    k_agg1   <<<nb_warp, TB>>>(n);
    k_agg2   <<<nb_warp, TB>>>(n);
    k_out    <<<nb_node, TB>>>(W2s, W2n, b2, out, n);
}